// round 11
// baseline (speedup 1.0000x reference)
#include <cuda_runtime.h>
#include <stdint.h>
#include <math.h>

#define BATCH  512
#define TLEN   32768
#define NTH    256
#define CHUNK  8192                  // samples per chunk (32 KB)
#define NCHUNK (TLEN / CHUNK)        // 4
#define LSUB   (CHUNK / NTH)         // 32 samples per thread per chunk
#define RSTR   33                    // padded smem row stride (floats)
#define BUFSZ  (NTH * RSTR)          // 8448 floats per buffer
// extras: warpsum 16 + entry 16 + carry 2(+6 pad) + scf 8 + sQ 32 = 80 floats
#define SMEM_FLOATS (2 * BUFSZ + 80)
#define SMEM_BYTES  (SMEM_FLOATS * 4)

// ---------------------------------------------------------------------------
// Helpers (identical to R4)
// ---------------------------------------------------------------------------
__device__ __forceinline__ void dsvf_step(float x, float b0, float b1, float b2,
                                          float na1, float na2,
                                          float& z1, float& z2, float& y) {
    y = fmaf(b0, x, z1);
    z1 = fmaf(na1, y, fmaf(b1, x, z2));
    z2 = fmaf(na2, y, b2 * x);
}

__device__ __forceinline__ void cp_async4(unsigned int dst, const float* src) {
    asm volatile("cp.async.ca.shared.global [%0], [%1], 4;\n" ::
                 "r"(dst), "l"(src));
}

// issue one chunk's loads as a cp.async group (coalesced, padded-transposed)
__device__ __forceinline__ void load_chunk(const float* __restrict__ g,
                                           unsigned int sbuf, int w, int l) {
#pragma unroll
    for (int i = 0; i < 32; i++) {
        int e = (w << 10) + (i << 5) + l;      // chunk-local element index
        int row = e >> 5, col = e & 31;        // row r = thread r's data
        cp_async4(sbuf + (unsigned int)(row * RSTR + col) * 4u, g + e);
    }
    asm volatile("cp.async.commit_group;\n");
}

// intra-warp inclusive scan of 2-vector state with matrix monoid (Q in regs)
__device__ __forceinline__ void warp_scan(float& s1, float& s2,
                                          const float Q[6][4], int l) {
#pragma unroll
    for (int d = 0; d < 5; d++) {
        int o = 1 << d;
        float u1 = __shfl_up_sync(0xffffffffu, s1, o);
        float u2 = __shfl_up_sync(0xffffffffu, s2, o);
        if (l >= o) {
            s1 = fmaf(Q[d][0], u1, fmaf(Q[d][1], u2, s1));
            s2 = fmaf(Q[d][2], u1, fmaf(Q[d][3], u2, s2));
        }
    }
}

// ---------------------------------------------------------------------------
// Fused kernel: R4's pipeline + per-CTA inlined coefficient setup
// ---------------------------------------------------------------------------
__global__ void __launch_bounds__(NTH)
dsvf_fused_kernel(const float* __restrict__ x, float* __restrict__ out,
                  const float* __restrict__ g_raw, const float* __restrict__ r_raw,
                  const float* __restrict__ m_hp, const float* __restrict__ m_bp,
                  const float* __restrict__ m_lp) {
    extern __shared__ float sm[];
    float* buf0    = sm;
    float* buf1    = sm + BUFSZ;
    float* warpsum = sm + 2 * BUFSZ;   // 16 floats
    float* entry   = warpsum + 16;     // 16 floats
    float* carry   = entry + 16;       // 2 floats (+6 pad)
    float* scf     = carry + 8;        // 8 floats (5 used)
    float* sQ      = scf + 8;          // 32 floats: Q[k] = A^(32*2^k), k=0..5

    const int tid = threadIdx.x;
    const int w = tid >> 5, l = tid & 31;
    const int row_id = blockIdx.x;

    const float* xrow = x + (size_t)row_id * TLEN;
    float* yrow = out + (size_t)row_id * TLEN;

    unsigned int sb0 = (unsigned int)__cvta_generic_to_shared(buf0);
    unsigned int sb1 = (unsigned int)__cvta_generic_to_shared(buf1);

    // prefetch chunk 0 first so the scalar coeff math overlaps the loads
    load_chunk(xrow, sb0, w, l);

    if (tid == 0) {
        float sg = 1.0f / (1.0f + expf(-g_raw[0]));
        float gg = tanf(3.14159265358979323846f * sg * 0.5f);
        float rr = log1pf(expf(r_raw[0]));
        float g2 = gg * gg;
        float hp = m_hp[0], bp = m_bp[0], lp = m_lp[0];

        float b0 = g2 * lp + gg * bp + hp;
        float b1 = 2.0f * g2 * lp - 2.0f * hp;
        float b2 = g2 * lp - gg * bp + hp;
        float a0 = g2 + 2.0f * rr * gg + 1.0f;
        float a1 = 2.0f * g2 - 2.0f;
        float a2 = g2 - 2.0f * rr * gg + 1.0f;
        float inv = 1.0f / a0;
        b0 *= inv; b1 *= inv; b2 *= inv; a1 *= inv; a2 *= inv;
        scf[0] = b0; scf[1] = b1; scf[2] = b2; scf[3] = a1; scf[4] = a2;

        // A = [[-a1,1],[-a2,0]];  Q[k] = A^(32*2^k), k = 0..5
        double m00 = -(double)a1, m01 = 1.0, m10 = -(double)a2, m11 = 0.0;
        for (int i = 0; i < 5; i++) {   // A -> A^32
            double t00 = m00 * m00 + m01 * m10, t01 = m00 * m01 + m01 * m11;
            double t10 = m10 * m00 + m11 * m10, t11 = m10 * m01 + m11 * m11;
            m00 = t00; m01 = t01; m10 = t10; m11 = t11;
        }
        sQ[0] = (float)m00; sQ[1] = (float)m01; sQ[2] = (float)m10; sQ[3] = (float)m11;
        for (int k = 1; k < 6; k++) {
            double t00 = m00 * m00 + m01 * m10, t01 = m00 * m01 + m01 * m11;
            double t10 = m10 * m00 + m11 * m10, t11 = m10 * m01 + m11 * m11;
            m00 = t00; m01 = t01; m10 = t10; m11 = t11;
            sQ[4 * k + 0] = (float)m00; sQ[4 * k + 1] = (float)m01;
            sQ[4 * k + 2] = (float)m10; sQ[4 * k + 3] = (float)m11;
        }
        carry[0] = 0.0f; carry[1] = 0.0f;
    }
    __syncthreads();   // scf/sQ/carry published (chunk-0 prefetch still in flight)

    // per-thread register copies, exactly as R4 held them
    const float b0 = scf[0], b1 = scf[1], b2 = scf[2];
    const float na1 = -scf[3], na2 = -scf[4];
    float Q[6][4];
#pragma unroll
    for (int k = 0; k < 6; k++)
#pragma unroll
        for (int j = 0; j < 4; j++) Q[k][j] = sQ[4 * k + j];

#pragma unroll
    for (int c = 0; c < NCHUNK; c++) {
        float* b = (c & 1) ? buf1 : buf0;
        if (c + 1 < NCHUNK) {
            load_chunk(xrow + (c + 1) * CHUNK, ((c + 1) & 1) ? sb1 : sb0, w, l);
            asm volatile("cp.async.wait_group 1;\n");
        } else {
            asm volatile("cp.async.wait_group 0;\n");
        }
        __syncthreads();   // chunk c resident for all threads

        // ---- pass 1: zero-state sub-block -> v ----
        float* r = b + tid * RSTR;
        float z1 = 0.0f, z2 = 0.0f, yv;
#pragma unroll
        for (int k = 0; k < LSUB; k++)
            dsvf_step(r[k], b0, b1, b2, na1, na2, z1, z2, yv);
        const float v1 = z1, v2 = z2;

        // ---- scan #1: intra-warp inclusive ----
        float s1 = v1, s2 = v2;
        warp_scan(s1, s2, Q, l);
        if (l == 31) { warpsum[2 * w] = s1; warpsum[2 * w + 1] = s2; }
        __syncthreads();

        // ---- serial cross-warp scan (thread 0) ----
        if (tid == 0) {
            float t1 = carry[0], t2 = carry[1];
#pragma unroll
            for (int u = 0; u < 8; u++) {
                entry[2 * u] = t1; entry[2 * u + 1] = t2;
                float w1 = warpsum[2 * u], w2 = warpsum[2 * u + 1];
                float n1 = fmaf(Q[5][0], t1, fmaf(Q[5][1], t2, w1));
                float n2 = fmaf(Q[5][2], t1, fmaf(Q[5][3], t2, w2));
                t1 = n1; t2 = n2;
            }
            carry[0] = t1; carry[1] = t2;
        }
        __syncthreads();

        // ---- scan #2 with warp-entry injected into lane 0 ----
        const float E1 = entry[2 * w], E2 = entry[2 * w + 1];
        s1 = v1; s2 = v2;
        if (l == 0) {
            s1 = fmaf(Q[0][0], E1, fmaf(Q[0][1], E2, s1));
            s2 = fmaf(Q[0][2], E1, fmaf(Q[0][3], E2, s2));
        }
        warp_scan(s1, s2, Q, l);
        float p1 = __shfl_up_sync(0xffffffffu, s1, 1);
        float p2 = __shfl_up_sync(0xffffffffu, s2, 1);
        if (l == 0) { p1 = E1; p2 = E2; }

        // ---- pass 2: true entry state, write y in place ----
        z1 = p1; z2 = p2;
#pragma unroll
        for (int k = 0; k < LSUB; k++) {
            float xv = r[k];
            dsvf_step(xv, b0, b1, b2, na1, na2, z1, z2, yv);
            r[k] = yv;
        }
        __syncthreads();   // all rows written before cross-thread store reads

        // ---- coalesced store (conflict-free scalar LDS -> STG.128) ----
        float* go = yrow + c * CHUNK;
#pragma unroll
        for (int i = 0; i < 8; i++) {
            int f = (w << 8) + (i << 5) + l;   // float4 index in chunk
            int e = f << 2;
            int rr = e >> 5, cc = e & 31;
            float4 o;
            o.x = b[rr * RSTR + cc + 0];
            o.y = b[rr * RSTR + cc + 1];
            o.z = b[rr * RSTR + cc + 2];
            o.w = b[rr * RSTR + cc + 3];
            reinterpret_cast<float4*>(go)[f] = o;
        }
        __syncthreads();   // buffer free before it is reloaded (chunk c+2)
    }
}

// ---------------------------------------------------------------------------
extern "C" void kernel_launch(void* const* d_in, const int* in_sizes, int n_in,
                              void* d_out, int out_size) {
    const float* x    = (const float*)d_in[0];
    const float* g    = (const float*)d_in[1];
    const float* r    = (const float*)d_in[2];
    const float* m_hp = (const float*)d_in[3];
    const float* m_bp = (const float*)d_in[4];
    const float* m_lp = (const float*)d_in[5];
    float* out = (float*)d_out;

    cudaFuncSetAttribute(dsvf_fused_kernel,
                         cudaFuncAttributeMaxDynamicSharedMemorySize, SMEM_BYTES);

    dsvf_fused_kernel<<<BATCH, NTH, SMEM_BYTES>>>(x, out, g, r, m_hp, m_bp, m_lp);
}

// round 12
// speedup vs baseline: 1.0313x; 1.0313x over previous
#include <cuda_runtime.h>
#include <stdint.h>
#include <math.h>

#define BATCH  512
#define TLEN   32768
#define NTH    512
#define NW     16                    // warps per CTA
#define CHUNK  8192                  // samples per chunk (32 KB)
#define NCHUNK (TLEN / CHUNK)        // 4
#define LSUB   16                    // samples per thread per chunk
#define NBUF   2
#define BUFSZ  (NTH * 16)            // 8192 floats, swizzled 64B rows
// extras: warpsum 32 + scf 8 + sQ 36 + pad = 80 floats
#define SMEM_FLOATS (NBUF * BUFSZ + 80)
#define SMEM_BYTES  (SMEM_FLOATS * 4)

// ---------------------------------------------------------------------------
__device__ __forceinline__ void dsvf_step(float x, float b0, float b1, float b2,
                                          float na1, float na2,
                                          float& z1, float& z2, float& y) {
    y = fmaf(b0, x, z1);
    z1 = fmaf(na1, y, fmaf(b1, x, z2));
    z2 = fmaf(na2, y, b2 * x);
}

__device__ __forceinline__ void cp_async16(unsigned int dst, const float* src) {
    asm volatile("cp.async.cg.shared.global [%0], [%1], 16;\n" ::
                 "r"(dst), "l"(src));
}

// stage one chunk into swizzled-transposed smem: element e -> row e>>4 (64B row),
// float4-group (e>>2)&3 stored at group ((e>>2)&3) ^ ((row>>1)&3)
__device__ __forceinline__ void load_chunk(const float* __restrict__ g,
                                           unsigned int sbuf, int tid) {
#pragma unroll
    for (int i = 0; i < 4; i++) {
        int f = i * NTH + tid;                    // float4 index in chunk
        int rr = f >> 2, cc = f & 3;
        unsigned int off = (unsigned int)((rr * 16 + ((cc ^ ((rr >> 1) & 3)) << 2)) * 4);
        cp_async16(sbuf + off, g + f * 4);
    }
    asm volatile("cp.async.commit_group;\n");
}

// intra-warp inclusive matrix-monoid scan (Q from smem, broadcast)
__device__ __forceinline__ void warp_scan(float& s1, float& s2,
                                          const float* sQ, int l) {
#pragma unroll
    for (int d = 0; d < 5; d++) {
        int o = 1 << d;
        float q0 = sQ[4 * d + 0], q1 = sQ[4 * d + 1];
        float q2 = sQ[4 * d + 2], q3 = sQ[4 * d + 3];
        float u1 = __shfl_up_sync(0xffffffffu, s1, o);
        float u2 = __shfl_up_sync(0xffffffffu, s2, o);
        if (l >= o) {
            s1 = fmaf(q0, u1, fmaf(q1, u2, s1));
            s2 = fmaf(q2, u1, fmaf(q3, u2, s2));
        }
    }
}

// ---------------------------------------------------------------------------
// One CTA per row, 512 threads, 4 chunk iterations, 3 barriers per iteration
// ---------------------------------------------------------------------------
__global__ void __launch_bounds__(NTH, 2)
dsvf_fused_kernel(const float* __restrict__ x, float* __restrict__ out,
                  const float* __restrict__ g_raw, const float* __restrict__ r_raw,
                  const float* __restrict__ m_hp, const float* __restrict__ m_bp,
                  const float* __restrict__ m_lp) {
    extern __shared__ float sm[];
    float* warpsum = sm + NBUF * BUFSZ;   // 32 floats (16 warps x 2)
    float* scf     = warpsum + 32;        // 8 floats (5 used)
    float* sQ      = scf + 8;             // 36 floats: Q[k] = A^(16*2^k), k=0..8

    const int tid = threadIdx.x;
    const int w = tid >> 5, l = tid & 31;
    const int swz = (tid >> 1) & 3;       // this thread's row swizzle

    const float* xrow = x + (size_t)blockIdx.x * TLEN;
    float* yrow = out + (size_t)blockIdx.x * TLEN;

    unsigned int sb[NBUF];
#pragma unroll
    for (int i = 0; i < NBUF; i++)
        sb[i] = (unsigned int)__cvta_generic_to_shared(sm + i * BUFSZ);

    // prefetch chunks 0 and 1 so the scalar setup math overlaps the loads
    load_chunk(xrow,         sb[0], tid);
    load_chunk(xrow + CHUNK, sb[1], tid);

    if (tid == 0) {
        float sg = 1.0f / (1.0f + expf(-g_raw[0]));
        float gg = tanf(3.14159265358979323846f * sg * 0.5f);
        float rr = log1pf(expf(r_raw[0]));
        float g2 = gg * gg;
        float hp = m_hp[0], bp = m_bp[0], lp = m_lp[0];

        float b0 = g2 * lp + gg * bp + hp;
        float b1 = 2.0f * g2 * lp - 2.0f * hp;
        float b2 = g2 * lp - gg * bp + hp;
        float a0 = g2 + 2.0f * rr * gg + 1.0f;
        float a1 = 2.0f * g2 - 2.0f;
        float a2 = g2 - 2.0f * rr * gg + 1.0f;
        float inv = 1.0f / a0;
        b0 *= inv; b1 *= inv; b2 *= inv; a1 *= inv; a2 *= inv;
        scf[0] = b0; scf[1] = b1; scf[2] = b2; scf[3] = a1; scf[4] = a2;

        // A = [[-a1,1],[-a2,0]];  Q[k] = A^(16*2^k), k = 0..8
        double m00 = -(double)a1, m01 = 1.0, m10 = -(double)a2, m11 = 0.0;
        for (int i = 0; i < 4; i++) {   // A -> A^16
            double t00 = m00 * m00 + m01 * m10, t01 = m00 * m01 + m01 * m11;
            double t10 = m10 * m00 + m11 * m10, t11 = m10 * m01 + m11 * m11;
            m00 = t00; m01 = t01; m10 = t10; m11 = t11;
        }
        sQ[0] = (float)m00; sQ[1] = (float)m01; sQ[2] = (float)m10; sQ[3] = (float)m11;
        for (int k = 1; k < 9; k++) {
            double t00 = m00 * m00 + m01 * m10, t01 = m00 * m01 + m01 * m11;
            double t10 = m10 * m00 + m11 * m10, t11 = m10 * m01 + m11 * m11;
            m00 = t00; m01 = t01; m10 = t10; m11 = t11;
            sQ[4 * k + 0] = (float)m00; sQ[4 * k + 1] = (float)m01;
            sQ[4 * k + 2] = (float)m10; sQ[4 * k + 3] = (float)m11;
        }
    }
    __syncthreads();   // scf/sQ published (prefetches still in flight)

    const float b0 = scf[0], b1 = scf[1], b2 = scf[2];
    const float na1 = -scf[3], na2 = -scf[4];

    // ---- per-lane matrix P = A^(16*l), exclusive (powers of A commute) ----
    float P00 = sQ[0], P01 = sQ[1], P10 = sQ[2], P11 = sQ[3];   // A^16
#pragma unroll
    for (int d = 0; d < 5; d++) {
        int o = 1 << d;
        float u00 = __shfl_up_sync(0xffffffffu, P00, o);
        float u01 = __shfl_up_sync(0xffffffffu, P01, o);
        float u10 = __shfl_up_sync(0xffffffffu, P10, o);
        float u11 = __shfl_up_sync(0xffffffffu, P11, o);
        if (l >= o) {
            float n00 = P00 * u00 + P01 * u10, n01 = P00 * u01 + P01 * u11;
            float n10 = P10 * u00 + P11 * u10, n11 = P10 * u01 + P11 * u11;
            P00 = n00; P01 = n01; P10 = n10; P11 = n11;
        }
    }
    {   // exclusive shift; lane 0 = identity
        float e00 = __shfl_up_sync(0xffffffffu, P00, 1);
        float e01 = __shfl_up_sync(0xffffffffu, P01, 1);
        float e10 = __shfl_up_sync(0xffffffffu, P10, 1);
        float e11 = __shfl_up_sync(0xffffffffu, P11, 1);
        if (l == 0) { e00 = 1.f; e01 = 0.f; e10 = 0.f; e11 = 1.f; }
        P00 = e00; P01 = e01; P10 = e10; P11 = e11;
    }

    float c1 = 0.f, c2 = 0.f;   // chunk carry (identical in every thread)

#pragma unroll
    for (int c = 0; c < NCHUNK; c++) {
        float* b = sm + (c & 1) * BUFSZ;
        if (c == 0) asm volatile("cp.async.wait_group 1;\n");   // chunk 0 done, 1 flying
        else        asm volatile("cp.async.wait_group 0;\n");   // chunk c done
        __syncthreads();   // [BAR1] chunk c resident; buffer (c+1)&1 fully drained

        // refill: chunk c+1 load was issued earlier; issue chunk c+1's SUCCESSOR's
        // buffer use — i.e. at iter c (>=1) issue load of chunk c+1 into (c+1)&1.
        // (At c==0, chunk 1 was prefetched before the loop.)
        if (c >= 1 && c + 1 < NCHUNK)
            load_chunk(xrow + (c + 1) * CHUNK, sb[(c + 1) & 1], tid);

        // ---- pass 1: zero-state sub-block -> per-thread final state ----
        const float4* rp = reinterpret_cast<const float4*>(b + tid * 16);
        float z1 = 0.f, z2 = 0.f, yv;
#pragma unroll
        for (int k = 0; k < 4; k++) {
            float4 xv = rp[k ^ swz];
            dsvf_step(xv.x, b0, b1, b2, na1, na2, z1, z2, yv);
            dsvf_step(xv.y, b0, b1, b2, na1, na2, z1, z2, yv);
            dsvf_step(xv.z, b0, b1, b2, na1, na2, z1, z2, yv);
            dsvf_step(xv.w, b0, b1, b2, na1, na2, z1, z2, yv);
        }

        // ---- intra-warp inclusive scan of per-thread final states ----
        float s1 = z1, s2 = z2;
        warp_scan(s1, s2, sQ, l);
        if (l == 31) { warpsum[2 * w] = s1; warpsum[2 * w + 1] = s2; }
        __syncthreads();   // [BAR2] warpsums visible

        // ---- cross-warp scan over 16 warp totals, redundantly in EVERY warp ----
        float t1 = 0.f, t2 = 0.f;
        if (l < NW) { t1 = warpsum[2 * l]; t2 = warpsum[2 * l + 1]; }
        if (l == 0) {   // fold carry: t0 = Q5*c + t0  (Q5 = A^512 = warp block)
            t1 = fmaf(sQ[20], c1, fmaf(sQ[21], c2, t1));
            t2 = fmaf(sQ[22], c1, fmaf(sQ[23], c2, t2));
        }
#pragma unroll
        for (int d = 0; d < 4; d++) {   // levels use Q[5+d] = A^(512*2^d)
            int o = 1 << d;
            float q0 = sQ[4 * (5 + d) + 0], q1 = sQ[4 * (5 + d) + 1];
            float q2 = sQ[4 * (5 + d) + 2], q3 = sQ[4 * (5 + d) + 3];
            float u1 = __shfl_up_sync(0xffffffffu, t1, o);
            float u2 = __shfl_up_sync(0xffffffffu, t2, o);
            if (l >= o && l < NW) {
                t1 = fmaf(q0, u1, fmaf(q1, u2, t1));
                t2 = fmaf(q2, u1, fmaf(q3, u2, t2));
            }
        }
        // warp entry E = inclusive total of warp w-1 (carry for w==0)
        float E1 = __shfl_sync(0xffffffffu, t1, (w > 0) ? (w - 1) : 0);
        float E2 = __shfl_sync(0xffffffffu, t2, (w > 0) ? (w - 1) : 0);
        if (w == 0) { E1 = c1; E2 = c2; }
        // next chunk's carry = inclusive total of warp 15
        c1 = __shfl_sync(0xffffffffu, t1, NW - 1);
        c2 = __shfl_sync(0xffffffffu, t2, NW - 1);

        // ---- thread entry state = s_{l-1} + P_l * E ----
        float p1 = __shfl_up_sync(0xffffffffu, s1, 1);
        float p2 = __shfl_up_sync(0xffffffffu, s2, 1);
        if (l == 0) { p1 = 0.f; p2 = 0.f; }
        z1 = fmaf(P00, E1, fmaf(P01, E2, p1));
        z2 = fmaf(P10, E1, fmaf(P11, E2, p2));

        // ---- pass 2: filter with true entry state, write y in place ----
        float4* wp = reinterpret_cast<float4*>(b + tid * 16);
#pragma unroll
        for (int k = 0; k < 4; k++) {
            float4 xv = rp[k ^ swz];
            float4 o;
            dsvf_step(xv.x, b0, b1, b2, na1, na2, z1, z2, o.x);
            dsvf_step(xv.y, b0, b1, b2, na1, na2, z1, z2, o.y);
            dsvf_step(xv.z, b0, b1, b2, na1, na2, z1, z2, o.z);
            dsvf_step(xv.w, b0, b1, b2, na1, na2, z1, z2, o.w);
            wp[k ^ swz] = o;
        }
        __syncthreads();   // [BAR3] all rows written before cross-thread store reads

        // ---- coalesced store (swizzled LDS.128 -> STG.128) ----
        float4* go4 = reinterpret_cast<float4*>(yrow + c * CHUNK);
#pragma unroll
        for (int i = 0; i < 4; i++) {
            int f = i * NTH + tid;
            int rr = f >> 2, cc = f & 3;
            go4[f] = reinterpret_cast<const float4*>(b + rr * 16)[cc ^ ((rr >> 1) & 3)];
        }
        // no trailing barrier: next iteration's BAR1 proves the drain before refill
    }
}

// ---------------------------------------------------------------------------
extern "C" void kernel_launch(void* const* d_in, const int* in_sizes, int n_in,
                              void* d_out, int out_size) {
    const float* x    = (const float*)d_in[0];
    const float* g    = (const float*)d_in[1];
    const float* r    = (const float*)d_in[2];
    const float* m_hp = (const float*)d_in[3];
    const float* m_bp = (const float*)d_in[4];
    const float* m_lp = (const float*)d_in[5];
    float* out = (float*)d_out;

    cudaFuncSetAttribute(dsvf_fused_kernel,
                         cudaFuncAttributeMaxDynamicSharedMemorySize, SMEM_BYTES);

    dsvf_fused_kernel<<<BATCH, NTH, SMEM_BYTES>>>(x, out, g, r, m_hp, m_bp, m_lp);
}

// round 13
// speedup vs baseline: 1.2244x; 1.1873x over previous
#include <cuda_runtime.h>
#include <stdint.h>
#include <math.h>

#define BATCH  512
#define TLEN   32768
#define CHUNK  4096                  // samples per chunk (16 KB) per warp
#define NCHUNK (TLEN / CHUNK)        // 8
#define NBUF   3                     // triple buffer, depth-2 prefetch
#define SMEM_BYTES (NBUF * CHUNK * 4)   // 48 KB per (single-warp) CTA

// ---------------------------------------------------------------------------
__device__ __forceinline__ void cp_async16(unsigned int dst, const float* src) {
    asm volatile("cp.async.cg.shared.global [%0], [%1], 16;\n" ::
                 "r"(dst), "l"(src));
}

// Swizzled layout: logical float4 index f (0..1023) of a chunk, owner row
// r = f>>5 (lane r's 128 samples), within-row k = f&31, stored at physical
// float4 index r*32 + (k ^ r).  Conflict-free for both coalesced (fixed r,
// lanes = k) and per-lane (fixed r = lane, k = 0..31) .128 access.
__device__ __forceinline__ void load_chunk(const float* __restrict__ g,
                                           unsigned int sbuf, int t) {
#pragma unroll
    for (int j = 0; j < 32; j++) {
        // owner row j, lane t supplies k = t  ->  phys j*32 + (t^j)
        cp_async16(sbuf + (unsigned int)((j * 32 + (t ^ j)) * 16),
                   g + (j * 32 + t) * 4);
    }
    asm volatile("cp.async.commit_group;\n");
}

// ---------------------------------------------------------------------------
// One WARP per row.  512 CTAs x 32 threads.  No __syncthreads anywhere.
// ---------------------------------------------------------------------------
__global__ void __launch_bounds__(32)
dsvf_warp_kernel(const float* __restrict__ x, float* __restrict__ out,
                 const float* __restrict__ g_raw, const float* __restrict__ r_raw,
                 const float* __restrict__ m_hp, const float* __restrict__ m_bp,
                 const float* __restrict__ m_lp) {
    extern __shared__ float sm[];
    const int t = threadIdx.x;            // lane

    const float* xrow = x + (size_t)blockIdx.x * TLEN;
    float* yrow = out + (size_t)blockIdx.x * TLEN;

    unsigned int sb[NBUF];
#pragma unroll
    for (int i = 0; i < NBUF; i++)
        sb[i] = (unsigned int)__cvta_generic_to_shared(sm + i * CHUNK);

    // prefetch chunks 0..2 first; scalar setup below overlaps the loads
    load_chunk(xrow,             sb[0], t);
    load_chunk(xrow + CHUNK,     sb[1], t);
    load_chunk(xrow + 2 * CHUNK, sb[2], t);

    // ---- coefficients (computed redundantly by all lanes — free in SIMT) ----
    float sg = 1.0f / (1.0f + expf(-g_raw[0]));
    float gg = tanf(3.14159265358979323846f * sg * 0.5f);
    float rr = log1pf(expf(r_raw[0]));
    float g2 = gg * gg;
    float hp = m_hp[0], bp = m_bp[0], lp = m_lp[0];

    float b0 = g2 * lp + gg * bp + hp;
    float b1 = 2.0f * g2 * lp - 2.0f * hp;
    float b2 = g2 * lp - gg * bp + hp;
    float a0f = g2 + 2.0f * rr * gg + 1.0f;
    float a1 = 2.0f * g2 - 2.0f;
    float a2 = g2 - 2.0f * rr * gg + 1.0f;
    float inv = 1.0f / a0f;
    b0 *= inv; b1 *= inv; b2 *= inv; a1 *= inv; a2 *= inv;

    const float na1 = -a1;
    const float c1 = b1 - a1 * b0;        // input vector c of s' = A s + c x
    const float c2 = b2 - a2 * b0;

    // pairwise (A^2) step constants, in double for safety
    double da1 = a1, da2 = a2, dc1 = c1, dc2 = c2;
    const float A200 = (float)(da1 * da1 - da2);
    const float A201 = (float)(-da1);
    const float A210 = (float)(da1 * da2);
    const float A211 = (float)(-da2);
    const float d1   = (float)(-da1 * dc1 + dc2);   // (A c)_1
    const float d2   = (float)(-da2 * dc1);         // (A c)_2

    // Q[k] = A^(128 * 2^k), k = 0..4  (lane block = 128 samples)
    float Q[5][4];
    {
        double m00 = -da1, m01 = 1.0, m10 = -da2, m11 = 0.0;
#pragma unroll
        for (int i = 0; i < 7; i++) {     // A -> A^128
            double t00 = m00 * m00 + m01 * m10, t01 = m00 * m01 + m01 * m11;
            double t10 = m10 * m00 + m11 * m10, t11 = m10 * m01 + m11 * m11;
            m00 = t00; m01 = t01; m10 = t10; m11 = t11;
        }
        Q[0][0] = (float)m00; Q[0][1] = (float)m01;
        Q[0][2] = (float)m10; Q[0][3] = (float)m11;
#pragma unroll
        for (int k = 1; k < 5; k++) {
            double t00 = m00 * m00 + m01 * m10, t01 = m00 * m01 + m01 * m11;
            double t10 = m10 * m00 + m11 * m10, t11 = m10 * m01 + m11 * m11;
            m00 = t00; m01 = t01; m10 = t10; m11 = t11;
            Q[k][0] = (float)m00; Q[k][1] = (float)m01;
            Q[k][2] = (float)m10; Q[k][3] = (float)m11;
        }
    }

    float carry1 = 0.f, carry2 = 0.f;

#pragma unroll 1
    for (int c = 0; c < NCHUNK; c++) {
        float* b = sm + (c % NBUF) * CHUNK;
        // chunk c's group must be complete (groups issued: 0..min(c+2,7))
        if (c < NCHUNK - 2)       asm volatile("cp.async.wait_group 2;\n");
        else if (c == NCHUNK - 2) asm volatile("cp.async.wait_group 1;\n");
        else                      asm volatile("cp.async.wait_group 0;\n");
        __syncwarp();   // cross-lane visibility of all lanes' cp.asyncs

        const float4* row = reinterpret_cast<const float4*>(b) + t * 32;

        // ---- pass 1: zero-state pairwise recurrence over 128 samples ----
        float z1 = 0.f, z2 = 0.f;
#pragma unroll
        for (int k = 0; k < 32; k++) {
            float4 v = row[k ^ t];
            {   // pair (v.x, v.y)
                float t1 = fmaf(d1, v.x, c1 * v.y);
                float t2 = fmaf(d2, v.x, c2 * v.y);
                float n1 = fmaf(A200, z1, fmaf(A201, z2, t1));
                float n2 = fmaf(A210, z1, fmaf(A211, z2, t2));
                z1 = n1; z2 = n2;
            }
            {   // pair (v.z, v.w)
                float t1 = fmaf(d1, v.z, c1 * v.w);
                float t2 = fmaf(d2, v.z, c2 * v.w);
                float n1 = fmaf(A200, z1, fmaf(A201, z2, t1));
                float n2 = fmaf(A210, z1, fmaf(A211, z2, t2));
                z1 = n1; z2 = n2;
            }
        }

        // ---- warp scan (matrix monoid) with carry injected at lane 0 ----
        float s1 = z1, s2 = z2;
        if (t == 0) {   // v0' = A^128 * carry + v0
            s1 = fmaf(Q[0][0], carry1, fmaf(Q[0][1], carry2, s1));
            s2 = fmaf(Q[0][2], carry1, fmaf(Q[0][3], carry2, s2));
        }
#pragma unroll
        for (int d = 0; d < 5; d++) {
            int o = 1 << d;
            float u1 = __shfl_up_sync(0xffffffffu, s1, o);
            float u2 = __shfl_up_sync(0xffffffffu, s2, o);
            if (t >= o) {
                s1 = fmaf(Q[d][0], u1, fmaf(Q[d][1], u2, s1));
                s2 = fmaf(Q[d][2], u1, fmaf(Q[d][3], u2, s2));
            }
        }
        // entry state for this lane = inclusive of lane-1 (carry for lane 0)
        float p1 = __shfl_up_sync(0xffffffffu, s1, 1);
        float p2 = __shfl_up_sync(0xffffffffu, s2, 1);
        if (t == 0) { p1 = carry1; p2 = carry2; }
        carry1 = __shfl_sync(0xffffffffu, s1, 31);
        carry2 = __shfl_sync(0xffffffffu, s2, 31);

        // ---- pass 2: pairwise filter with true entry state, y in place ----
        z1 = p1; z2 = p2;
        float4* wrow = reinterpret_cast<float4*>(b) + t * 32;
#pragma unroll
        for (int k = 0; k < 32; k++) {
            float4 v = row[k ^ t];
            float4 o;
            {   // pair (v.x, v.y)
                o.x = fmaf(b0, v.x, z1);
                float u = fmaf(c1, v.x, z2);
                o.y = fmaf(b0, v.y, fmaf(na1, z1, u));
                float t1 = fmaf(d1, v.x, c1 * v.y);
                float t2 = fmaf(d2, v.x, c2 * v.y);
                float n1 = fmaf(A200, z1, fmaf(A201, z2, t1));
                float n2 = fmaf(A210, z1, fmaf(A211, z2, t2));
                z1 = n1; z2 = n2;
            }
            {   // pair (v.z, v.w)
                o.z = fmaf(b0, v.z, z1);
                float u = fmaf(c1, v.z, z2);
                o.w = fmaf(b0, v.w, fmaf(na1, z1, u));
                float t1 = fmaf(d1, v.z, c1 * v.w);
                float t2 = fmaf(d2, v.z, c2 * v.w);
                float n1 = fmaf(A200, z1, fmaf(A201, z2, t1));
                float n2 = fmaf(A210, z1, fmaf(A211, z2, t2));
                z1 = n1; z2 = n2;
            }
            wrow[k ^ t] = o;
        }
        __syncwarp();   // all lanes' y rows written before cross-lane store reads

        // ---- coalesced store (swizzled LDS.128 -> STG.128) ----
        float4* go = reinterpret_cast<float4*>(yrow + c * CHUNK);
        const float4* bb = reinterpret_cast<const float4*>(b);
#pragma unroll
        for (int j = 0; j < 32; j++)
            go[j * 32 + t] = bb[j * 32 + (t ^ j)];
        __syncwarp();   // all lanes done reading this buffer

        // refill this buffer with chunk c+3
        if (c + NBUF < NCHUNK)
            load_chunk(xrow + (c + NBUF) * CHUNK, sb[c % NBUF], t);
    }
}

// ---------------------------------------------------------------------------
extern "C" void kernel_launch(void* const* d_in, const int* in_sizes, int n_in,
                              void* d_out, int out_size) {
    const float* x    = (const float*)d_in[0];
    const float* g    = (const float*)d_in[1];
    const float* r    = (const float*)d_in[2];
    const float* m_hp = (const float*)d_in[3];
    const float* m_bp = (const float*)d_in[4];
    const float* m_lp = (const float*)d_in[5];
    float* out = (float*)d_out;

    cudaFuncSetAttribute(dsvf_warp_kernel,
                         cudaFuncAttributeMaxDynamicSharedMemorySize, SMEM_BYTES);

    dsvf_warp_kernel<<<BATCH, 32, SMEM_BYTES>>>(x, out, g, r, m_hp, m_bp, m_lp);
}

// round 15
// speedup vs baseline: 1.2255x; 1.0009x over previous
#include <cuda_runtime.h>
#include <stdint.h>
#include <math.h>

#define BATCH  512
#define TLEN   32768
#define CHUNK  4096                  // samples per chunk (16 KB) per warp
#define NCHUNK (TLEN / CHUNK)        // 8
#define NBUF   3                     // triple buffer, depth-2 prefetch
// 3 chunk buffers + 64 floats of entry states
#define SMEM_BYTES ((NBUF * CHUNK + 64) * 4)

// ---------------------------------------------------------------------------
__device__ __forceinline__ void cp_async16(unsigned int dst, const float* src) {
    asm volatile("cp.async.cg.shared.global [%0], [%1], 16;\n" ::
                 "r"(dst), "l"(src));
}

// Swizzled layout: logical float4 index f (0..1023) of a chunk, owner row
// r = f>>5 (lane r's 128 samples), within-row k = f&31, stored at physical
// float4 index r*32 + (k ^ r).  Conflict-free for both coalesced (fixed k,
// lanes = rows) and per-lane (fixed r = lane, k = 0..31) .128 access.
__device__ __forceinline__ void load_chunk(const float* __restrict__ g,
                                           unsigned int sbuf, int t) {
#pragma unroll
    for (int j = 0; j < 32; j++) {
        cp_async16(sbuf + (unsigned int)((j * 32 + (t ^ j)) * 16),
                   g + (j * 32 + t) * 4);
    }
    asm volatile("cp.async.commit_group;\n");
}

// ---------------------------------------------------------------------------
// One WARP per row.  512 CTAs x 32 threads.  No __syncthreads anywhere.
// Single recurrence pass; entry-state correction applied during the store.
// ---------------------------------------------------------------------------
__global__ void __launch_bounds__(32)
dsvf_warp_kernel(const float* __restrict__ x, float* __restrict__ out,
                 const float* __restrict__ g_raw, const float* __restrict__ r_raw,
                 const float* __restrict__ m_hp, const float* __restrict__ m_bp,
                 const float* __restrict__ m_lp) {
    extern __shared__ float sm[];
    float* entry = sm + NBUF * CHUNK;     // 64 floats: per-lane entry states
    const int t = threadIdx.x;            // lane

    const float* xrow = x + (size_t)blockIdx.x * TLEN;
    float* yrow = out + (size_t)blockIdx.x * TLEN;

    unsigned int sb[NBUF];
#pragma unroll
    for (int i = 0; i < NBUF; i++)
        sb[i] = (unsigned int)__cvta_generic_to_shared(sm + i * CHUNK);

    // prefetch chunks 0..2 first; scalar setup below overlaps the loads
    load_chunk(xrow,             sb[0], t);
    load_chunk(xrow + CHUNK,     sb[1], t);
    load_chunk(xrow + 2 * CHUNK, sb[2], t);

    // ---- coefficients (computed redundantly by all lanes — free in SIMT) ----
    float sg = 1.0f / (1.0f + expf(-g_raw[0]));
    float gg = tanf(3.14159265358979323846f * sg * 0.5f);
    float rr = log1pf(expf(r_raw[0]));
    float g2 = gg * gg;
    float hp = m_hp[0], bp = m_bp[0], lp = m_lp[0];

    float b0 = g2 * lp + gg * bp + hp;
    float b1 = 2.0f * g2 * lp - 2.0f * hp;
    float b2 = g2 * lp - gg * bp + hp;
    float a0f = g2 + 2.0f * rr * gg + 1.0f;
    float a1 = 2.0f * g2 - 2.0f;
    float a2 = g2 - 2.0f * rr * gg + 1.0f;
    float inv = 1.0f / a0f;
    b0 *= inv; b1 *= inv; b2 *= inv; a1 *= inv; a2 *= inv;

    const float na1 = -a1;
    const float c1 = b1 - a1 * b0;        // input vector c of s' = A s + c x
    const float c2 = b2 - a2 * b0;

    // pairwise (A^2) step constants, in double for safety
    double da1 = a1, da2 = a2, dc1 = c1, dc2 = c2;
    const float A200 = (float)(da1 * da1 - da2);
    const float A201 = (float)(-da1);
    const float A210 = (float)(da1 * da2);
    const float A211 = (float)(-da2);
    const float d1   = (float)(-da1 * dc1 + dc2);   // (A c)_1
    const float d2   = (float)(-da2 * dc1);         // (A c)_2

    // Q[k] = A^(128 * 2^k), k = 0..4  (lane block = 128 samples)
    float Q[5][4];
    {
        double m00 = -da1, m01 = 1.0, m10 = -da2, m11 = 0.0;
#pragma unroll
        for (int i = 0; i < 7; i++) {     // A -> A^128
            double t00 = m00 * m00 + m01 * m10, t01 = m00 * m01 + m01 * m11;
            double t10 = m10 * m00 + m11 * m10, t11 = m10 * m01 + m11 * m11;
            m00 = t00; m01 = t01; m10 = t10; m11 = t11;
        }
        Q[0][0] = (float)m00; Q[0][1] = (float)m01;
        Q[0][2] = (float)m10; Q[0][3] = (float)m11;
#pragma unroll
        for (int k = 1; k < 5; k++) {
            double t00 = m00 * m00 + m01 * m10, t01 = m00 * m01 + m01 * m11;
            double t10 = m10 * m00 + m11 * m10, t11 = m10 * m01 + m11 * m11;
            m00 = t00; m01 = t01; m10 = t10; m11 = t11;
            Q[k][0] = (float)m00; Q[k][1] = (float)m01;
            Q[k][2] = (float)m10; Q[k][3] = (float)m11;
        }
    }

    // ---- per-lane correction rows H: h(s) = e1^T A^s for s = 4t .. 4t+3 ----
    // R = A^(4t) via exclusive lane-product scan of A^4 (powers commute),
    // then h(4t) = row1 of R, advanced by A for the next three samples.
    float H1x, H1y, H1z, H1w, H2x, H2y, H2z, H2w;
    {
        double m00 = -da1, m01 = 1.0, m10 = -da2, m11 = 0.0;
#pragma unroll
        for (int i = 0; i < 2; i++) {     // A -> A^4
            double t00 = m00 * m00 + m01 * m10, t01 = m00 * m01 + m01 * m11;
            double t10 = m10 * m00 + m11 * m10, t11 = m10 * m01 + m11 * m11;
            m00 = t00; m01 = t01; m10 = t10; m11 = t11;
        }
        float P00 = (float)m00, P01 = (float)m01, P10 = (float)m10, P11 = (float)m11;
#pragma unroll
        for (int d = 0; d < 5; d++) {
            int o = 1 << d;
            float u00 = __shfl_up_sync(0xffffffffu, P00, o);
            float u01 = __shfl_up_sync(0xffffffffu, P01, o);
            float u10 = __shfl_up_sync(0xffffffffu, P10, o);
            float u11 = __shfl_up_sync(0xffffffffu, P11, o);
            if (t >= o) {
                float n00 = P00 * u00 + P01 * u10, n01 = P00 * u01 + P01 * u11;
                float n10 = P10 * u00 + P11 * u10, n11 = P10 * u01 + P11 * u11;
                P00 = n00; P01 = n01; P10 = n10; P11 = n11;
            }
        }
        float e00 = __shfl_up_sync(0xffffffffu, P00, 1);
        float e01 = __shfl_up_sync(0xffffffffu, P01, 1);
        if (t == 0) { e00 = 1.f; e01 = 0.f; }
        // h advance: (h1,h2) -> (-a1*h1 - a2*h2, h1)
        float h1 = e00, h2 = e01;
        H1x = h1; H2x = h2;
        { float n = fmaf(na1, h1, -a2 * h2); h2 = h1; h1 = n; }
        H1y = h1; H2y = h2;
        { float n = fmaf(na1, h1, -a2 * h2); h2 = h1; h1 = n; }
        H1z = h1; H2z = h2;
        { float n = fmaf(na1, h1, -a2 * h2); h2 = h1; h1 = n; }
        H1w = h1; H2w = h2;
    }

    float carry1 = 0.f, carry2 = 0.f;

#pragma unroll 1
    for (int c = 0; c < NCHUNK; c++) {
        float* b = sm + (c % NBUF) * CHUNK;
        if (c < NCHUNK - 2)       asm volatile("cp.async.wait_group 2;\n");
        else if (c == NCHUNK - 2) asm volatile("cp.async.wait_group 1;\n");
        else                      asm volatile("cp.async.wait_group 0;\n");
        __syncwarp();   // cross-lane visibility of all lanes' cp.asyncs

        float4* row = reinterpret_cast<float4*>(b) + t * 32;

        // ---- single pass: zero-state recurrence, y0 written in place ----
        float z1 = 0.f, z2 = 0.f;
#pragma unroll
        for (int k = 0; k < 32; k++) {
            float4 v = row[k ^ t];
            float4 o;
            {   // pair (v.x, v.y)
                o.x = fmaf(b0, v.x, z1);
                float u = fmaf(c1, v.x, z2);
                o.y = fmaf(b0, v.y, fmaf(na1, z1, u));
                float t1 = fmaf(d1, v.x, c1 * v.y);
                float t2 = fmaf(d2, v.x, c2 * v.y);
                float n1 = fmaf(A200, z1, fmaf(A201, z2, t1));
                float n2 = fmaf(A210, z1, fmaf(A211, z2, t2));
                z1 = n1; z2 = n2;
            }
            {   // pair (v.z, v.w)
                o.z = fmaf(b0, v.z, z1);
                float u = fmaf(c1, v.z, z2);
                o.w = fmaf(b0, v.w, fmaf(na1, z1, u));
                float t1 = fmaf(d1, v.z, c1 * v.w);
                float t2 = fmaf(d2, v.z, c2 * v.w);
                float n1 = fmaf(A200, z1, fmaf(A201, z2, t1));
                float n2 = fmaf(A210, z1, fmaf(A211, z2, t2));
                z1 = n1; z2 = n2;
            }
            row[k ^ t] = o;
        }

        // ---- warp scan (matrix monoid) with carry injected at lane 0 ----
        float s1 = z1, s2 = z2;
        if (t == 0) {   // v0' = A^128 * carry + v0
            s1 = fmaf(Q[0][0], carry1, fmaf(Q[0][1], carry2, s1));
            s2 = fmaf(Q[0][2], carry1, fmaf(Q[0][3], carry2, s2));
        }
#pragma unroll
        for (int d = 0; d < 5; d++) {
            int o = 1 << d;
            float u1 = __shfl_up_sync(0xffffffffu, s1, o);
            float u2 = __shfl_up_sync(0xffffffffu, s2, o);
            if (t >= o) {
                s1 = fmaf(Q[d][0], u1, fmaf(Q[d][1], u2, s1));
                s2 = fmaf(Q[d][2], u1, fmaf(Q[d][3], u2, s2));
            }
        }
        // entry state for this lane = inclusive of lane-1 (carry for lane 0)
        float p1 = __shfl_up_sync(0xffffffffu, s1, 1);
        float p2 = __shfl_up_sync(0xffffffffu, s2, 1);
        if (t == 0) { p1 = carry1; p2 = carry2; }
        carry1 = __shfl_sync(0xffffffffu, s1, 31);
        carry2 = __shfl_sync(0xffffffffu, s2, 31);

        // publish entry states for the store-time correction
        entry[2 * t] = p1;
        entry[2 * t + 1] = p2;
        __syncwarp();   // y0 rows + entry[] visible to all lanes

        // ---- store with inline correction: y = y0 + H * e(owner) ----
        float4* go = reinterpret_cast<float4*>(yrow + c * CHUNK);
        const float4* bb = reinterpret_cast<const float4*>(b);
#pragma unroll
        for (int j = 0; j < 32; j++) {
            float4 v = bb[j * 32 + (t ^ j)];     // owner j's samples 4t..4t+3
            float e1 = entry[2 * j], e2 = entry[2 * j + 1];   // LDS broadcast
            float4 o;
            o.x = fmaf(H1x, e1, fmaf(H2x, e2, v.x));
            o.y = fmaf(H1y, e1, fmaf(H2y, e2, v.y));
            o.z = fmaf(H1z, e1, fmaf(H2z, e2, v.z));
            o.w = fmaf(H1w, e1, fmaf(H2w, e2, v.w));
            go[j * 32 + t] = o;
        }
        __syncwarp();   // all lanes done reading this buffer

        // refill this buffer with chunk c+3
        if (c + NBUF < NCHUNK)
            load_chunk(xrow + (c + NBUF) * CHUNK, sb[c % NBUF], t);
    }
}

// ---------------------------------------------------------------------------
extern "C" void kernel_launch(void* const* d_in, const int* in_sizes, int n_in,
                              void* d_out, int out_size) {
    const float* x    = (const float*)d_in[0];
    const float* g    = (const float*)d_in[1];
    const float* r    = (const float*)d_in[2];
    const float* m_hp = (const float*)d_in[3];
    const float* m_bp = (const float*)d_in[4];
    const float* m_lp = (const float*)d_in[5];
    float* out = (float*)d_out;

    cudaFuncSetAttribute(dsvf_warp_kernel,
                         cudaFuncAttributeMaxDynamicSharedMemorySize, SMEM_BYTES);

    dsvf_warp_kernel<<<BATCH, 32, SMEM_BYTES>>>(x, out, g, r, m_hp, m_bp, m_lp);
}